// round 12
// baseline (speedup 1.0000x reference)
#include <cuda_runtime.h>
#include <cuda_bf16.h>

#define T_LEN   8192
#define F_DIM   80
#define BINS    24
#define NT      512
#define PER     (T_LEN / NT)     // 16
#define HORIZON 0.35f

__global__ __launch_bounds__(NT) void rhythm_kernel(
    const float* __restrict__ feat,
    const int*   __restrict__ mask,
    const float* __restrict__ phase,
    float*       __restrict__ out,
    const int    ws)
{
    const int b   = blockIdx.x;
    const int B   = gridDim.x;
    const int tid = threadIdx.x;

    __shared__ int   s_csum[T_LEN];          // 32 KB: raw mask, then inclusive cumsum
    __shared__ float s_trace[BINS * F_DIM];  // 7.5 KB
    __shared__ int   s_left[BINS], s_right[BINS];
    __shared__ float s_alpha[BINS];
    __shared__ int   s_wsum[NT / 32];
    __shared__ int   s_rises;

    if (tid == 0) s_rises = 0;

    // ---- load mask into SMEM (vectorized, coalesced) ----
    const int4* mb4 = (const int4*)(mask + (size_t)b * T_LEN);
    for (int t = tid; t < T_LEN / 4; t += NT) {
        int4 m = mb4[t];
        s_csum[4 * t + 0] = m.x;
        s_csum[4 * t + 1] = m.y;
        s_csum[4 * t + 2] = m.z;
        s_csum[4 * t + 3] = m.w;
    }
    __syncthreads();

    // ---- rises = count of 0->1 transitions (prev padded with 0) ----
    int rises = 0;
    for (int t = tid; t < T_LEN; t += NT) {
        int m = s_csum[t];
        int p = (t == 0) ? 0 : s_csum[t - 1];
        rises += (m == 1 && p == 0);
    }
    #pragma unroll
    for (int o = 16; o; o >>= 1) rises += __shfl_down_sync(0xffffffffu, rises, o);
    if ((tid & 31) == 0) atomicAdd(&s_rises, rises);

    // ---- per-thread sequential scan over its contiguous chunk ----
    const int base = tid * PER;
    int v[PER];
    int run = 0;
    #pragma unroll
    for (int k = 0; k < PER; k++) { run += s_csum[base + k]; v[k] = run; }

    // warp-level inclusive scan of per-thread sums
    const int lane = tid & 31, warp = tid >> 5;
    int x = run;
    #pragma unroll
    for (int o = 1; o < 32; o <<= 1) {
        int y = __shfl_up_sync(0xffffffffu, x, o);
        if (lane >= o) x += y;
    }
    if (lane == 31) s_wsum[warp] = x;
    __syncthreads();
    if (tid < NT / 32) {
        int w  = s_wsum[tid];
        int xx = w;
        #pragma unroll
        for (int o = 1; o < NT / 32; o <<= 1) {
            int y = __shfl_up_sync(0x0000ffffu, xx, o);
            if (tid >= o) xx += y;
        }
        s_wsum[tid] = xx - w;   // exclusive warp prefix
    }
    __syncthreads();
    const int prefix = s_wsum[warp] + (x - run);   // exclusive prefix for this thread
    #pragma unroll
    for (int k = 0; k < PER; k++) s_csum[base + k] = v[k] + prefix;
    __syncthreads();

    const int   total       = s_csum[T_LEN - 1];
    const float maxtot      = fmaxf((float)total, 1.0f);
    const bool  use_uniform = (total <= 0);

    // XLA AlgebraicSimplifier: divide(csum, broadcast(scalar)) ->
    // multiply(csum, broadcast(divide(1, scalar))). The hoisted scalar
    // divide is IEEE: recip = fl(1/maxtot); progress[k] = RN(csum[k]*recip)
    // (double-rounded -> per-element tie signs, != fl(csum/total)).
    const float recip = __fdiv_rn(1.0f, maxtot);

    // ---- searchsorted(progress, targets, 'left') ----
    // targets: IEEE mul-form linspace t[i] = RN(i * fl(1/23)), endpoint 1.0.
    if (tid < BINS) {
        const float delta_t = __fdiv_rn(1.0f, (float)(BINS - 1));
        const float target  = (tid == BINS - 1)
                            ? 1.0f
                            : __fmul_rn((float)tid, delta_t);
        const float delta_u = __fdiv_rn(1.0f, (float)(T_LEN - 1));
        int lo = 0, hi = T_LEN;
        while (lo < hi) {
            int   mid = (lo + hi) >> 1;
            float p   = use_uniform
                      ? ((mid == T_LEN - 1) ? 1.0f : __fmul_rn((float)mid, delta_u))
                      : __fmul_rn((float)s_csum[mid], recip);
            if (p >= target) hi = mid; else lo = mid + 1;
        }
        const int right = lo;
        int   l  = min(max(right - 1, 0), T_LEN - 1);
        int   rc = min(right, T_LEN - 1);
        float a;
        if (right <= 0)            { l = 0;         rc = 0;         a = 0.0f; }
        else if (right >= T_LEN)   { l = T_LEN - 1; rc = T_LEN - 1; a = 0.0f; }
        else {
            float lp = use_uniform
                     ? ((l == T_LEN - 1) ? 1.0f : __fmul_rn((float)l, delta_u))
                     : __fmul_rn((float)s_csum[l],  recip);
            float rp = use_uniform
                     ? ((rc == T_LEN - 1) ? 1.0f : __fmul_rn((float)rc, delta_u))
                     : __fmul_rn((float)s_csum[rc], recip);
            float denom = fmaxf(fabsf(__fadd_rn(rp, -lp)), 1e-6f);
            // elementwise tensor divide (not hoistable) -> IEEE div.rn
            a = fminf(fmaxf(__fdiv_rn(__fadd_rn(target, -lp), denom), 0.0f), 1.0f);
        }
        s_left[tid]  = l;
        s_right[tid] = rc;
        s_alpha[tid] = a;
    }
    __syncthreads();

    // ---- gather + blend the 24-bin trace; write to SMEM and GMEM ----
    const float* fb = feat + (size_t)b * T_LEN * F_DIM;
    const size_t trace_off = (size_t)B * ws * F_DIM;
    float* out_trace = out + trace_off + (size_t)b * BINS * F_DIM;
    for (int idx = tid; idx < BINS * F_DIM; idx += NT) {
        int   j = idx / F_DIM, f = idx - j * F_DIM;
        float a  = s_alpha[j];
        float fl = fb[(size_t)s_left[j]  * F_DIM + f];
        float fr = fb[(size_t)s_right[j] * F_DIM + f];
        float val = __fadd_rn(__fmul_rn(fl, __fadd_rn(1.0f, -a)),
                              __fmul_rn(fr, a));
        s_trace[idx]   = val;
        out_trace[idx] = val;
    }
    __syncthreads();

    // ---- sample the trace at phase_ptr + linspace(0, HORIZON, ws) ----
    const float ph      = phase[b];
    const float delta_o = __fdiv_rn(HORIZON, (float)(ws - 1));
    float* out_sampled = out + (size_t)b * ws * F_DIM;
    for (int idx = tid; idx < ws * F_DIM; idx += NT) {
        int   i = idx / F_DIM, f = idx - i * F_DIM;
        float off    = (i == ws - 1) ? HORIZON : __fmul_rn((float)i, delta_o);
        float pos    = fminf(fmaxf(__fadd_rn(ph, off), 0.0f), 1.0f);
        float scaled = __fmul_rn(pos, (float)(BINS - 1));
        int   l = min(max((int)floorf(scaled), 0), BINS - 1);
        int   r = min(l + 1, BINS - 1);
        float a = __fadd_rn(scaled, -(float)l);
        float gl = s_trace[l * F_DIM + f];
        float gr = s_trace[r * F_DIM + f];
        out_sampled[idx] = __fadd_rn(__fmul_rn(gl, __fadd_rn(1.0f, -a)),
                                     __fmul_rn(gr, a));
    }

    // ---- run_mean (elementwise [B]/[B] divide -> IEEE) ----
    if (tid == 0) {
        int   rr = s_rises;
        float rm = (rr > 0) ? __fdiv_rn((float)total, fmaxf((float)rr, 1.0f)) : 0.0f;
        out[trace_off + (size_t)B * BINS * F_DIM + b] = rm;
    }
}

extern "C" void kernel_launch(void* const* d_in, const int* in_sizes, int n_in,
                              void* d_out, int out_size) {
    const float* feat = (const float*)d_in[0];

    // Bind mask/phase by SIZE, not position (robust to metadata ordering).
    const int*   mask;
    const float* phase;
    int B;
    if (in_sizes[1] > in_sizes[2]) {        // order: feat, mask, phase
        mask  = (const int*)d_in[1];
        phase = (const float*)d_in[2];
        B     = in_sizes[2];
    } else {                                 // order: feat, phase, mask
        phase = (const float*)d_in[1];
        mask  = (const int*)d_in[2];
        B     = in_sizes[1];
    }

    // Derive window_size from out_size = B*(ws*F + BINS*F + 1).
    const int ws = (out_size / B - 1) / F_DIM - BINS;

    float* out = (float*)d_out;
    rhythm_kernel<<<B, NT>>>(feat, mask, phase, out, ws);
}

// round 15
// speedup vs baseline: 1.2250x; 1.2250x over previous
#include <cuda_runtime.h>
#include <cuda_bf16.h>

#define T_LEN   8192
#define F_DIM   80
#define BINS    24
#define NT      512
#define PER     (T_LEN / NT)     // 16
#define HORIZON 0.35f
#define NW      (NT / 32)        // 16 warps

// Bank-conflict-free padded index: one pad word per 16. Blocked access
// tid*16+k maps to 17*tid+k; gcd(17,32)=1 -> bijective over lanes.
#define IDX(i)  ((i) + ((i) >> 4))
#define CSUM_SZ (T_LEN + (T_LEN >> 4))

__global__ __launch_bounds__(NT) void rhythm_kernel(
    const float* __restrict__ feat,
    const int*   __restrict__ mask,
    const float* __restrict__ phase,
    float*       __restrict__ out,
    const int    ws)
{
    const int b   = blockIdx.x;
    const int B   = gridDim.x;
    const int tid = threadIdx.x;

    __shared__ int   s_csum[CSUM_SZ];        // 34 KB padded cumsum
    __shared__ float s_trace[BINS * F_DIM];  // 7.5 KB
    __shared__ int   s_left[BINS], s_right[BINS];
    __shared__ float s_alpha[BINS];
    __shared__ int   s_wsum[NW];
    __shared__ int   s_wrises[NW];           // per-warp rises (no atomics)

    // ---- blocked GMEM load: each thread reads its own 16 mask values ----
    const int* mb  = mask + (size_t)b * T_LEN;
    const int  base = tid * PER;
    int m[PER];
    {
        const int4* p4 = (const int4*)(mb + base);
        #pragma unroll
        for (int q = 0; q < PER / 4; q++) {
            int4 w = p4[q];
            m[4 * q + 0] = w.x; m[4 * q + 1] = w.y;
            m[4 * q + 2] = w.z; m[4 * q + 3] = w.w;
        }
    }
    const int prev0 = (tid == 0) ? 0 : mb[base - 1];   // L1/L2 hit

    // ---- rises + local inclusive scan (registers only) ----
    int v[PER];
    const int lane = tid & 31, warp = tid >> 5;
    {
        int prev = prev0, rises = 0, run = 0;
        #pragma unroll
        for (int k = 0; k < PER; k++) {
            rises += (m[k] == 1 && prev == 0);
            prev   = m[k];
            run   += m[k];
            v[k]   = run;
        }
        #pragma unroll
        for (int o = 16; o; o >>= 1) rises += __shfl_down_sync(0xffffffffu, rises, o);
        if (lane == 0) s_wrises[warp] = rises;   // ordered by the barrier below

        // warp-level inclusive scan of per-thread sums
        int x = run;
        #pragma unroll
        for (int o = 1; o < 32; o <<= 1) {
            int y = __shfl_up_sync(0xffffffffu, x, o);
            if (lane >= o) x += y;
        }
        if (lane == 31) s_wsum[warp] = x;
        __syncthreads();
        if (tid < NW) {
            int w  = s_wsum[tid];
            int xx = w;
            #pragma unroll
            for (int o = 1; o < NW; o <<= 1) {
                int y = __shfl_up_sync(0x0000ffffu, xx, o);
                if (tid >= o) xx += y;
            }
            s_wsum[tid] = xx - w;            // exclusive warp prefix
        }
        __syncthreads();
        const int prefix = s_wsum[warp] + (x - run);
        // conflict-free scalar stores into padded layout (17-stride)
        #pragma unroll
        for (int k = 0; k < PER; k++) s_csum[IDX(base + k)] = v[k] + prefix;
    }
    __syncthreads();

    const int   total       = s_csum[IDX(T_LEN - 1)];
    const float maxtot      = fmaxf((float)total, 1.0f);
    const bool  use_uniform = (total <= 0);

    // XLA AlgebraicSimplifier: divide(csum, broadcast(scalar)) ->
    // multiply(csum, broadcast(divide(1, scalar))); hoisted divide is IEEE.
    const float recip = __fdiv_rn(1.0f, maxtot);

    // ---- searchsorted(progress, targets, 'left') ----
    if (tid < BINS) {
        const float delta_t = __fdiv_rn(1.0f, (float)(BINS - 1));
        const float target  = (tid == BINS - 1)
                            ? 1.0f
                            : __fmul_rn((float)tid, delta_t);
        const float delta_u = __fdiv_rn(1.0f, (float)(T_LEN - 1));
        int lo = 0, hi = T_LEN;
        while (lo < hi) {
            int   mid = (lo + hi) >> 1;
            float p   = use_uniform
                      ? ((mid == T_LEN - 1) ? 1.0f : __fmul_rn((float)mid, delta_u))
                      : __fmul_rn((float)s_csum[IDX(mid)], recip);
            if (p >= target) hi = mid; else lo = mid + 1;
        }
        const int right = lo;
        int   l  = min(max(right - 1, 0), T_LEN - 1);
        int   rc = min(right, T_LEN - 1);
        float a;
        if (right <= 0)            { l = 0;         rc = 0;         a = 0.0f; }
        else if (right >= T_LEN)   { l = T_LEN - 1; rc = T_LEN - 1; a = 0.0f; }
        else {
            float lp = use_uniform
                     ? ((l == T_LEN - 1) ? 1.0f : __fmul_rn((float)l, delta_u))
                     : __fmul_rn((float)s_csum[IDX(l)],  recip);
            float rp = use_uniform
                     ? ((rc == T_LEN - 1) ? 1.0f : __fmul_rn((float)rc, delta_u))
                     : __fmul_rn((float)s_csum[IDX(rc)], recip);
            float denom = fmaxf(fabsf(__fadd_rn(rp, -lp)), 1e-6f);
            a = fminf(fmaxf(__fdiv_rn(__fadd_rn(target, -lp), denom), 0.0f), 1.0f);
        }
        s_left[tid]  = l;
        s_right[tid] = rc;
        s_alpha[tid] = a;
    }
    __syncthreads();

    // ---- gather + blend the 24-bin trace; write to SMEM and GMEM ----
    const float* fb = feat + (size_t)b * T_LEN * F_DIM;
    const size_t trace_off = (size_t)B * ws * F_DIM;
    float* out_trace = out + trace_off + (size_t)b * BINS * F_DIM;
    #pragma unroll
    for (int i = 0; i < (BINS * F_DIM + NT - 1) / NT; i++) {
        int idx = tid + i * NT;
        if (idx < BINS * F_DIM) {
            int   j = idx / F_DIM, f = idx - j * F_DIM;
            float a  = s_alpha[j];
            float fl = fb[(size_t)s_left[j]  * F_DIM + f];
            float fr = fb[(size_t)s_right[j] * F_DIM + f];
            float val = __fadd_rn(__fmul_rn(fl, __fadd_rn(1.0f, -a)),
                                  __fmul_rn(fr, a));
            s_trace[idx]   = val;
            out_trace[idx] = val;
        }
    }
    __syncthreads();

    // ---- sample the trace at phase_ptr + linspace(0, HORIZON, ws) ----
    const float ph      = phase[b];
    const float delta_o = __fdiv_rn(HORIZON, (float)(ws - 1));
    float* out_sampled = out + (size_t)b * ws * F_DIM;
    for (int idx = tid; idx < ws * F_DIM; idx += NT) {
        int   i = idx / F_DIM, f = idx - i * F_DIM;
        float off    = (i == ws - 1) ? HORIZON : __fmul_rn((float)i, delta_o);
        float pos    = fminf(fmaxf(__fadd_rn(ph, off), 0.0f), 1.0f);
        float scaled = __fmul_rn(pos, (float)(BINS - 1));
        int   l = min(max((int)floorf(scaled), 0), BINS - 1);
        int   r = min(l + 1, BINS - 1);
        float a = __fadd_rn(scaled, -(float)l);
        float gl = s_trace[l * F_DIM + f];
        float gr = s_trace[r * F_DIM + f];
        out_sampled[idx] = __fadd_rn(__fmul_rn(gl, __fadd_rn(1.0f, -a)),
                                     __fmul_rn(gr, a));
    }

    // ---- run_mean (tid 0 sums per-warp rises; elementwise divide -> IEEE) ----
    if (tid == 0) {
        int rr = 0;
        #pragma unroll
        for (int w = 0; w < NW; w++) rr += s_wrises[w];
        float rm = (rr > 0) ? __fdiv_rn((float)total, fmaxf((float)rr, 1.0f)) : 0.0f;
        out[trace_off + (size_t)B * BINS * F_DIM + b] = rm;
    }
}

extern "C" void kernel_launch(void* const* d_in, const int* in_sizes, int n_in,
                              void* d_out, int out_size) {
    const float* feat = (const float*)d_in[0];

    // Bind mask/phase by SIZE, not position.
    const int*   mask;
    const float* phase;
    int B;
    if (in_sizes[1] > in_sizes[2]) {        // order: feat, mask, phase
        mask  = (const int*)d_in[1];
        phase = (const float*)d_in[2];
        B     = in_sizes[2];
    } else {                                 // order: feat, phase, mask
        phase = (const float*)d_in[1];
        mask  = (const int*)d_in[2];
        B     = in_sizes[1];
    }

    // Derive window_size from out_size = B*(ws*F + BINS*F + 1).
    const int ws = (out_size / B - 1) / F_DIM - BINS;

    float* out = (float*)d_out;
    rhythm_kernel<<<B, NT>>>(feat, mask, phase, out, ws);
}